// round 16
// baseline (speedup 1.0000x reference)
#include <cuda_runtime.h>
#include <cuda_fp16.h>
#include <cstdint>

#define B_ 256
#define T_ 100
#define D_ 4096
#define H_ 1024

#define BM 128
#define BN 64
#define BK 32
#define SA 40          // A stage row stride in halfs (R2/R4-proven conflict-free)
#define SBN 72         // B stage row stride in halfs (R4-proven conflict-free)
#define NTH 128
#define STAGES 3
#define SPLIT1 8
#define SPLIT2 2
#define ASZ (BM * SA)  // 5120 halfs
#define BSZ (BK * SBN) // 2304 halfs

// Scratch (static __device__; no dynamic allocation anywhere)
__device__ __align__(16) __half g_KFh[D_ * H_];              // KFinv fp16 [D,H] (K-major B, gemm1)
__device__ __align__(16) __half g_Zh[H_ * D_];               // Z fp16 [H,D]     (K-major B, gemm2)
__device__ __align__(16) __half g_diffh[B_ * D_];            // x_t - nb_t
__device__ __align__(16) __half g_hidh[B_ * H_];             // hidden fp16
__device__ __align__(16) float  g_hidpart[SPLIT1 * B_ * H_]; // gemm1 partials
__device__ __align__(16) float  g_g2part[SPLIT2 * B_ * D_];  // gemm2 partials
__device__ unsigned g_cnt1[32];     // gemm1 tile counters (zero-init)
__device__ unsigned g_cnt2[128];    // gemm2 tile counters (zero-init)

__device__ __forceinline__ uint32_t smem_u32(const void* p) {
    return (uint32_t)__cvta_generic_to_shared(p);
}
__device__ __forceinline__ void cpa16(uint32_t saddr, const void* g) {
    asm volatile("cp.async.cg.shared.global [%0], [%1], 16;\n" :: "r"(saddr), "l"(g));
}
__device__ __forceinline__ void cpa_commit() {
    asm volatile("cp.async.commit_group;\n");
}
__device__ __forceinline__ void cpa_wait1() {
    asm volatile("cp.async.wait_group 1;\n" ::: "memory");
}
__device__ __forceinline__ void mma16816(float* c, const unsigned* a, const unsigned* b) {
    asm volatile(
        "mma.sync.aligned.m16n8k16.row.col.f32.f16.f16.f32 "
        "{%0,%1,%2,%3},{%4,%5,%6,%7},{%8,%9},{%0,%1,%2,%3};\n"
        : "+f"(c[0]), "+f"(c[1]), "+f"(c[2]), "+f"(c[3])
        : "r"(a[0]), "r"(a[1]), "r"(a[2]), "r"(a[3]), "r"(b[0]), "r"(b[1]));
}
__device__ __forceinline__ void ldsm_x4(uint32_t addr, unsigned* r) {
    asm volatile("ldmatrix.sync.aligned.m8n8.x4.shared.b16 {%0,%1,%2,%3}, [%4];\n"
        : "=r"(r[0]), "=r"(r[1]), "=r"(r[2]), "=r"(r[3]) : "r"(addr));
}
__device__ __forceinline__ void ldsm_x4_t(uint32_t addr, unsigned* r) {
    asm volatile("ldmatrix.sync.aligned.m8n8.x4.trans.shared.b16 {%0,%1,%2,%3}, [%4];\n"
        : "=r"(r[0]), "=r"(r[1]), "=r"(r[2]), "=r"(r[3]) : "r"(addr));
}

// ---------------- GEMM mainloop ----------------
// C[128,64] += A[m0:, kbase:] * B[kbase:, n0:]
// A row-major [*, lda] fp16 (MxK); B row-major [*, ldb] fp16 (KxN, K-major).
// 4 warps as 2(m) x 2(n), warp tile 64x32: per kk16, 4x ldsm(A) + 2x ldsm.trans(B), 16 MMA.
// 3-stage cp.async ring (R2-proven), fill-early (R6-proven), one __syncthreads/iter.
__device__ __forceinline__ void run_gemm(
    const __half* __restrict__ Ag, int lda,
    const __half* __restrict__ Bg, int ldb,
    int m0, int n0, int kbase, int iters,
    float (&acc)[4][4][4])
{
    __shared__ __align__(16) __half As[STAGES][ASZ];
    __shared__ __align__(16) __half Bs[STAGES][BSZ];

    const int tid = threadIdx.x;
    const int lane = tid & 31;
    const int wid = tid >> 5;
    const int wm = (wid & 1) * 64;
    const int wn = (wid >> 1) * 32;

    // Loaders (128 threads):
    // A tile 128x32 halfs: thread owns row tid, 4 x cpa16
    // B tile 32x64 halfs: rows tid>>2, col chunk (tid&3)*16, 2 x cpa16
    const int br = tid >> 2, bc = (tid & 3) * 16;

    const __half* Ap = Ag + (size_t)(m0 + tid) * lda + kbase;
    const __half* Bp = Bg + (size_t)(kbase + br) * ldb + n0 + bc;

    auto fill = [&](int it) {
        const int slot = it % STAGES;
        const uint32_t a = smem_u32(&As[slot][tid * SA]);
        const __half* agp = Ap + it * BK;
        cpa16(a,      agp);
        cpa16(a + 16, agp + 8);
        cpa16(a + 32, agp + 16);
        cpa16(a + 48, agp + 24);
        const uint32_t b = smem_u32(&Bs[slot][br * SBN + bc]);
        const __half* bgp = Bp + (size_t)it * BK * ldb;
        cpa16(b,      bgp);
        cpa16(b + 16, bgp + 8);
    };
    fill(0); cpa_commit();
    fill(1); cpa_commit();

    // R2/R4-proven ldmatrix per-lane address components
    const int a_row  = (lane & 7) + ((lane >> 3) & 1) * 8;  // + wm + mf*16
    const int a_colo = (lane >> 4) * 8;                     // + kk
    const int b_rowo = (lane & 7) + ((lane >> 3) & 1) * 8;  // + kk
    const int b_colo = ((lane >> 4) & 1) * 8;               // + wn + nf2*16

#pragma unroll 1
    for (int it = 0; it < iters; ++it) {
        cpa_wait1();          // stage `it` landed (commits before wait = it+2)
        __syncthreads();
        // Refill slot (it+2)%3 == (it-1)%3: consumed at iter it-1, protected
        // by the barrier above. Loads overlap this iteration's compute.
        if (it + STAGES - 1 < iters) fill(it + STAGES - 1);
        cpa_commit();         // unconditional: keeps group<->stage numbering exact

        const __half* Asb = As[it % STAGES];
        const __half* Bsb = Bs[it % STAGES];
#pragma unroll
        for (int kk = 0; kk < BK; kk += 16) {
            unsigned bf[4][2];
#pragma unroll
            for (int nf2 = 0; nf2 < 2; ++nf2) {
                unsigned r[4];
                ldsm_x4_t(smem_u32(&Bsb[(kk + b_rowo) * SBN + wn + nf2 * 16 + b_colo]), r);
                bf[nf2 * 2][0]     = r[0]; bf[nf2 * 2][1]     = r[1];
                bf[nf2 * 2 + 1][0] = r[2]; bf[nf2 * 2 + 1][1] = r[3];
            }
            unsigned av[4][4];
#pragma unroll
            for (int mf = 0; mf < 4; ++mf)
                ldsm_x4(smem_u32(&Asb[(wm + mf * 16 + a_row) * SA + kk + a_colo]), av[mf]);
#pragma unroll
            for (int mf = 0; mf < 4; ++mf)
#pragma unroll
                for (int nf = 0; nf < 4; ++nf)
                    mma16816(acc[mf][nf], av[mf], bf[nf]);
        }
    }
}

// Store acc fragments as fp32 partial tile at outp (already offset to (m0,n0))
__device__ __forceinline__ void store_partial(float* __restrict__ outp, int ld,
                                              float (&acc)[4][4][4]) {
    const int lane = threadIdx.x & 31, wid = threadIdx.x >> 5;
    const int wm = (wid & 1) * 64, wn = (wid >> 1) * 32;
    const int r = lane >> 2, cp = (lane & 3) * 2;
#pragma unroll
    for (int mf = 0; mf < 4; ++mf)
#pragma unroll
        for (int nf = 0; nf < 4; ++nf) {
            const int m = wm + mf * 16 + r;
            const int n = wn + nf * 8 + cp;
            *(float2*)&outp[(size_t)m * ld + n]       = make_float2(acc[mf][nf][0], acc[mf][nf][1]);
            *(float2*)&outp[(size_t)(m + 8) * ld + n] = make_float2(acc[mf][nf][2], acc[mf][nf][3]);
        }
}

// ---------------- GEMM1 (split-K=8): hidden = diff @ KFinv + b_hidden ----------------
__global__ void __launch_bounds__(NTH) gemm1_k(const float* __restrict__ bh) {
    float acc[4][4][4];
#pragma unroll
    for (int i = 0; i < 4; ++i)
#pragma unroll
        for (int j = 0; j < 4; ++j)
#pragma unroll
            for (int k = 0; k < 4; ++k) acc[i][j][k] = 0.f;

    const int m0 = blockIdx.y * BM;
    const int n0 = blockIdx.x * BN;
    const int z = blockIdx.z;
    run_gemm(g_diffh, D_, g_KFh, H_, m0, n0, z * (D_ / SPLIT1), (D_ / SPLIT1) / BK, acc);

    store_partial(g_hidpart + (size_t)z * (B_ * H_) + (size_t)m0 * H_ + n0, H_, acc);

    // R7-proven split-K arrival barrier; last CTA reduces in fixed z-order
    __shared__ unsigned s_old;
    __threadfence();
    __syncthreads();
    if (threadIdx.x == 0)
        s_old = atomicAdd(&g_cnt1[blockIdx.y * 16 + blockIdx.x], 1u);
    __syncthreads();

    if (s_old == SPLIT1 - 1) {
        __threadfence();  // acquire
        const int m = m0 + threadIdx.x;
        const float* pbase = g_hidpart + (size_t)m * H_ + n0;
        __half* hrow = g_hidh + (size_t)m * H_ + n0;
#pragma unroll 1
        for (int j = 0; j < BN; j += 4) {
            float4 s = *(const float4*)&bh[n0 + j];
#pragma unroll
            for (int zz = 0; zz < SPLIT1; ++zz) {  // fixed z-order: deterministic
                const float4 p = *(const float4*)&pbase[(size_t)zz * (B_ * H_) + j];
                s.x += p.x; s.y += p.y; s.z += p.z; s.w += p.w;
            }
            const __half2 h0 = __floats2half2_rn(s.x, s.y);
            const __half2 h1 = __floats2half2_rn(s.z, s.w);
            uint2 pk;
            pk.x = *(const unsigned*)&h0;
            pk.y = *(const unsigned*)&h1;
            *(uint2*)&hrow[j] = pk;
        }
        if (threadIdx.x == 0)
            g_cnt1[blockIdx.y * 16 + blockIdx.x] = 0;  // reset for next launch/replay
    }
}

// ---------------- GEMM2 (split-K=2) + fused sigmoid / output / next diff ----------------
__global__ void __launch_bounds__(NTH) gemm2_k(const float* __restrict__ x,
                                               const float* __restrict__ b_out,
                                               float* __restrict__ out, int t) {
    float acc[4][4][4];
#pragma unroll
    for (int i = 0; i < 4; ++i)
#pragma unroll
        for (int j = 0; j < 4; ++j)
#pragma unroll
            for (int k = 0; k < 4; ++k) acc[i][j][k] = 0.f;

    const int m0 = blockIdx.y * BM;
    const int n0 = blockIdx.x * BN;
    const int z = blockIdx.z;
    run_gemm(g_hidh, H_, g_Zh, D_, m0, n0, z * (H_ / SPLIT2), (H_ / SPLIT2) / BK, acc);

    store_partial(g_g2part + (size_t)z * (B_ * D_) + (size_t)m0 * D_ + n0, D_, acc);

    __shared__ unsigned s_old;
    __threadfence();
    __syncthreads();
    if (threadIdx.x == 0)
        s_old = atomicAdd(&g_cnt2[blockIdx.y * 64 + blockIdx.x], 1u);
    __syncthreads();

    if (s_old == SPLIT2 - 1) {
        __threadfence();  // acquire
        const int m = m0 + threadIdx.x;
        const float* p0row = g_g2part + (size_t)m * D_ + n0;
        const float* p1row = p0row + (size_t)(B_ * D_);
        float* orow = out + (size_t)m * (T_ * D_) + (size_t)t * D_ + n0;
        const float* xrow = x + (size_t)m * (T_ * D_) + (size_t)(t + 1) * D_ + n0;
        __half* drow = g_diffh + (size_t)m * D_ + n0;
        const bool hasnext = (t + 1 < T_);
#pragma unroll 1
        for (int j = 0; j < BN; j += 4) {
            const float4 p0 = *(const float4*)&p0row[j];
            const float4 p1 = *(const float4*)&p1row[j];
            const float4 bb = *(const float4*)&b_out[n0 + j];
            float v0 = p0.x + p1.x + bb.x;   // fixed order: deterministic
            float v1 = p0.y + p1.y + bb.y;
            float v2 = p0.z + p1.z + bb.z;
            float v3 = p0.w + p1.w + bb.w;
            v0 = 1.f / (1.f + __expf(-v0));
            v1 = 1.f / (1.f + __expf(-v1));
            v2 = 1.f / (1.f + __expf(-v2));
            v3 = 1.f / (1.f + __expf(-v3));
            *(float4*)&orow[j] = make_float4(v0, v1, v2, v3);
            if (hasnext) {
                const float4 xv = *(const float4*)&xrow[j];
                const __half2 d0 = __floats2half2_rn(xv.x - v0, xv.y - v1);
                const __half2 d1 = __floats2half2_rn(xv.z - v2, xv.w - v3);
                uint2 pk;
                pk.x = *(const unsigned*)&d0;
                pk.y = *(const unsigned*)&d1;
                *(uint2*)&drow[j] = pk;
            }
        }
        if (threadIdx.x == 0)
            g_cnt2[blockIdx.y * 64 + blockIdx.x] = 0;
    }
}

// ---------------- one-time prep (R2-proven) ----------------
__global__ void convert_k(const float* __restrict__ Z, const float* __restrict__ KF) {
    const int i = blockIdx.x * blockDim.x + threadIdx.x;
    if (i < D_ * H_) {
        g_KFh[i] = __float2half(KF[i]);
        g_Zh[i]  = __float2half(Z[i]);
    }
}

// Step-0 diff: nb0 = b_out broadcast (no sigmoid on step 0, per reference)
__global__ void init_k(const float* __restrict__ x, const float* __restrict__ bo) {
    const int i = blockIdx.x * blockDim.x + threadIdx.x;  // over B_*D_
    const int b = i >> 12;
    const int k = i & (D_ - 1);
    g_diffh[i] = __float2half(x[(size_t)b * (T_ * D_) + k] - bo[k]);
}

extern "C" void kernel_launch(void* const* d_in, const int* in_sizes, int n_in,
                              void* d_out, int out_size) {
    const float* x  = (const float*)d_in[0];   // [B,T,D]
    const float* Z  = (const float*)d_in[1];   // [H,D]
    const float* bo = (const float*)d_in[2];   // [D]
    const float* KF = (const float*)d_in[3];   // [D,H]
    const float* bh = (const float*)d_in[4];   // [H]
    float* out = (float*)d_out;                // [B,T,D]

    convert_k<<<(D_ * H_ + 255) / 256, 256>>>(Z, KF);
    init_k<<<(B_ * D_ + 255) / 256, 256>>>(x, bo);

    dim3 g1(H_ / BN, B_ / BM, SPLIT1);  // (16, 2, 8) = 256 CTAs
    dim3 g2(D_ / BN, B_ / BM, SPLIT2);  // (64, 2, 2) = 256 CTAs
    for (int t = 0; t < T_; ++t) {
        gemm1_k<<<g1, NTH>>>(bh);
        gemm2_k<<<g2, NTH>>>(x, bo, out, t);
    }
}

// round 17
// speedup vs baseline: 2.4339x; 2.4339x over previous
#include <cuda_runtime.h>
#include <cuda_fp16.h>
#include <cstdint>

#define B_ 256
#define T_ 100
#define D_ 4096
#define H_ 1024

#define BM 64
#define BN 64
#define BK 64          // halfs per stage row = 128B = one full L2 line
#define NTH 128
#define STAGES 3
#define SPLIT1 4
#define ASZB 8192      // A stage bytes: 64 rows x 128B
#define BSZB 8192      // B stage bytes: 64 rows x 128B
#define STGB (ASZB + BSZB)

// Scratch (static __device__; no dynamic allocation anywhere)
__device__ __align__(16) __half g_KFh[D_ * H_];              // KFinv fp16 [D,H] (K-major B, gemm1)
__device__ __align__(16) __half g_Zh[H_ * D_];               // Z fp16 [H,D]     (K-major B, gemm2)
__device__ __align__(16) __half g_diffh[B_ * D_];            // x_t - nb_t
__device__ __align__(16) __half g_hidh[B_ * H_];             // hidden fp16
__device__ __align__(16) float  g_hidpart[SPLIT1 * B_ * H_]; // gemm1 split-K partials
__device__ unsigned g_cnt1[64];     // gemm1 tile counters (zero-init)

__device__ __forceinline__ uint32_t smem_u32(const void* p) {
    return (uint32_t)__cvta_generic_to_shared(p);
}
__device__ __forceinline__ void cpa16(uint32_t saddr, const void* g) {
    asm volatile("cp.async.cg.shared.global [%0], [%1], 16;\n" :: "r"(saddr), "l"(g));
}
__device__ __forceinline__ void cpa_commit() {
    asm volatile("cp.async.commit_group;\n");
}
__device__ __forceinline__ void cpa_wait1() {
    asm volatile("cp.async.wait_group 1;\n" ::: "memory");
}
__device__ __forceinline__ void mma16816(float* c, const unsigned* a, const unsigned* b) {
    asm volatile(
        "mma.sync.aligned.m16n8k16.row.col.f32.f16.f16.f32 "
        "{%0,%1,%2,%3},{%4,%5,%6,%7},{%8,%9},{%0,%1,%2,%3};\n"
        : "+f"(c[0]), "+f"(c[1]), "+f"(c[2]), "+f"(c[3])
        : "r"(a[0]), "r"(a[1]), "r"(a[2]), "r"(a[3]), "r"(b[0]), "r"(b[1]));
}
__device__ __forceinline__ void ldsm_x4(uint32_t addr, unsigned* r) {
    asm volatile("ldmatrix.sync.aligned.m8n8.x4.shared.b16 {%0,%1,%2,%3}, [%4];\n"
        : "=r"(r[0]), "=r"(r[1]), "=r"(r[2]), "=r"(r[3]) : "r"(addr));
}
__device__ __forceinline__ void ldsm_x4_t(uint32_t addr, unsigned* r) {
    asm volatile("ldmatrix.sync.aligned.m8n8.x4.trans.shared.b16 {%0,%1,%2,%3}, [%4];\n"
        : "=r"(r[0]), "=r"(r[1]), "=r"(r[2]), "=r"(r[3]) : "r"(addr));
}

// Swizzled smem byte offset for (row, chunk16) within a 64x128B tile.
// Identical to SMEM_SWIZZLE_128B(row*128 + chunk*16).
__device__ __forceinline__ uint32_t swz(int row, int chunk) {
    return (uint32_t)(row * 128 + ((chunk ^ (row & 7)) << 4));
}

// ---------------- GEMM mainloop ----------------
// C[64,64] += A[m0:, kbase:] * B[kbase:, n0:]
// A row-major [*, lda] fp16 (MxK); B row-major [*, ldb] fp16 (KxN, K-major).
// 4 warps as 2(m) x 2(n), warp tile 32x32 (R4-proven fragment math).
// BK=64: one 128B line per tile row; loader fully coalesced (4 rows/warp/instr).
// SW128 XOR swizzle; 3-stage cp.async ring, fill-early, one __syncthreads/iter.
__device__ __forceinline__ void run_gemm(
    unsigned char* smbuf,
    const __half* __restrict__ Ag, int lda,
    const __half* __restrict__ Bg, int ldb,
    int m0, int n0, int kbase, int iters,
    float (&acc)[2][4][4])
{
    const uint32_t sbase = smem_u32(smbuf);
    const int tid = threadIdx.x;
    const int lane = tid & 31;
    const int wid = tid >> 5;
    const int wm = (wid & 1) * 32;
    const int wn = (wid >> 1) * 32;

    // Loader: thread -> rows {rl, rl+16, rl+32, rl+48}, chunk c (16B).
    // A warp covers 4 consecutive rows fully (128B each) per instr: 4 wavefronts.
    const int rl = tid >> 3;       // 0..15
    const int lc = tid & 7;        // chunk 0..7
    const __half* Apb = Ag + (size_t)(m0 + rl) * lda + kbase + lc * 8;
    const __half* Bpb = Bg + (size_t)(kbase + rl) * ldb + n0 + lc * 8;

    auto fill = [&](int it) {
        const int slot = it % STAGES;
        const uint32_t abase = sbase + (uint32_t)slot * STGB;
        const uint32_t bbase = abase + ASZB;
        const __half* ag = Apb + it * BK;
        const __half* bg = Bpb + (size_t)it * BK * ldb;
#pragma unroll
        for (int p = 0; p < 4; ++p) {
            const int r = rl + p * 16;
            cpa16(abase + swz(r, lc), ag + (size_t)(p * 16) * lda);
            cpa16(bbase + swz(r, lc), bg + (size_t)(p * 16) * ldb);
        }
    };
    fill(0); cpa_commit();
    fill(1); cpa_commit();

    // R4-proven ldmatrix per-lane components
    const int a_row  = (lane & 7) + ((lane >> 3) & 1) * 8;  // + wm + mf*16
    const int axc    = (lane >> 4);                          // chunk offset (8 halfs)
    const int b_rowo = (lane & 7) + ((lane >> 3) & 1) * 8;   // + kk
    const int bxc    = (lane >> 4);                          // chunk offset (8 halfs)

#pragma unroll 1
    for (int it = 0; it < iters; ++it) {
        cpa_wait1();          // stage `it` landed
        __syncthreads();
        // Refill slot (it+2)%3 == (it-1)%3: consumed at iter it-1 (barrier above).
        if (it + STAGES - 1 < iters) fill(it + STAGES - 1);
        cpa_commit();         // unconditional: group<->stage numbering stays exact

        const uint32_t sAs = sbase + (uint32_t)(it % STAGES) * STGB;
        const uint32_t sBs = sAs + ASZB;
#pragma unroll
        for (int kk = 0; kk < BK; kk += 16) {
            unsigned bf[4][2];
#pragma unroll
            for (int nf2 = 0; nf2 < 2; ++nf2) {
                unsigned r[4];
                // B row = kk + b_rowo, chunk = (wn + nf2*16)/8 + bxc
                ldsm_x4_t(sBs + swz(kk + b_rowo, ((wn + nf2 * 16) >> 3) + bxc), r);
                bf[nf2 * 2][0]     = r[0]; bf[nf2 * 2][1]     = r[1];
                bf[nf2 * 2 + 1][0] = r[2]; bf[nf2 * 2 + 1][1] = r[3];
            }
            unsigned av[2][4];
#pragma unroll
            for (int mf = 0; mf < 2; ++mf)
                ldsm_x4(sAs + swz(wm + mf * 16 + a_row, (kk >> 3) + axc), av[mf]);
#pragma unroll
            for (int mf = 0; mf < 2; ++mf)
#pragma unroll
                for (int nf = 0; nf < 4; ++nf)
                    mma16816(acc[mf][nf], av[mf], bf[nf]);
        }
    }
}

// ---------------- GEMM1 (split-K=4): hidden = diff @ KFinv + b_hidden ----------------
__global__ void __launch_bounds__(NTH) gemm1_k(const float* __restrict__ bh) {
    __shared__ __align__(1024) unsigned char smbuf[STAGES * STGB];
    float acc[2][4][4];
#pragma unroll
    for (int i = 0; i < 2; ++i)
#pragma unroll
        for (int j = 0; j < 4; ++j)
#pragma unroll
            for (int k = 0; k < 4; ++k) acc[i][j][k] = 0.f;

    const int m0 = blockIdx.y * BM;
    const int n0 = blockIdx.x * BN;
    const int z = blockIdx.z;
    run_gemm(smbuf, g_diffh, D_, g_KFh, H_, m0, n0, z * (D_ / SPLIT1), (D_ / SPLIT1) / BK, acc);

    // store fp32 partial tile (R4-proven fragment->tile mapping)
    {
        float* outp = g_hidpart + (size_t)z * (B_ * H_) + (size_t)m0 * H_ + n0;
        const int lane = threadIdx.x & 31, wid = threadIdx.x >> 5;
        const int wm = (wid & 1) * 32, wn = (wid >> 1) * 32;
        const int r = lane >> 2, cp = (lane & 3) * 2;
#pragma unroll
        for (int mf = 0; mf < 2; ++mf)
#pragma unroll
            for (int nf = 0; nf < 4; ++nf) {
                const int m = wm + mf * 16 + r;
                const int n = wn + nf * 8 + cp;
                *(float2*)&outp[(size_t)m * H_ + n]       = make_float2(acc[mf][nf][0], acc[mf][nf][1]);
                *(float2*)&outp[(size_t)(m + 8) * H_ + n] = make_float2(acc[mf][nf][2], acc[mf][nf][3]);
            }
    }

    // split-K arrival barrier; alias counter-broadcast slot onto dead tile smem
    unsigned* s_old = (unsigned*)smbuf;
    __threadfence();
    __syncthreads();   // all warps done with tiles AND partial stores issued
    if (threadIdx.x == 0)
        *s_old = atomicAdd(&g_cnt1[blockIdx.y * 16 + blockIdx.x], 1u);
    __syncthreads();

    if (*s_old == SPLIT1 - 1) {
        __threadfence();  // acquire
        const int m = m0 + (threadIdx.x >> 1);
        const int c0 = n0 + (threadIdx.x & 1) * 32;
        const float* pbase = g_hidpart + (size_t)m * H_ + c0;
        __half* hrow = g_hidh + (size_t)m * H_ + c0;
#pragma unroll 1
        for (int j = 0; j < 32; j += 4) {
            float4 s = *(const float4*)&bh[c0 + j];
#pragma unroll
            for (int zz = 0; zz < SPLIT1; ++zz) {  // fixed z-order: deterministic
                const float4 p = *(const float4*)&pbase[(size_t)zz * (B_ * H_) + j];
                s.x += p.x; s.y += p.y; s.z += p.z; s.w += p.w;
            }
            const __half2 h0 = __floats2half2_rn(s.x, s.y);
            const __half2 h1 = __floats2half2_rn(s.z, s.w);
            uint2 pk;
            pk.x = *(const unsigned*)&h0;
            pk.y = *(const unsigned*)&h1;
            *(uint2*)&hrow[j] = pk;
        }
        if (threadIdx.x == 0)
            g_cnt1[blockIdx.y * 16 + blockIdx.x] = 0;  // reset for next launch/replay
    }
}

// ---------------- GEMM2 (no split) + fused sigmoid / output / next diff ----------------
__global__ void __launch_bounds__(NTH) gemm2_k(const float* __restrict__ x,
                                               const float* __restrict__ b_out,
                                               float* __restrict__ out, int t) {
    __shared__ __align__(1024) unsigned char smbuf[STAGES * STGB];
    float acc[2][4][4];
#pragma unroll
    for (int i = 0; i < 2; ++i)
#pragma unroll
        for (int j = 0; j < 4; ++j)
#pragma unroll
            for (int k = 0; k < 4; ++k) acc[i][j][k] = 0.f;

    const int m0 = blockIdx.y * BM;
    const int n0 = blockIdx.x * BN;
    run_gemm(smbuf, g_hidh, H_, g_Zh, D_, m0, n0, 0, H_ / BK, acc);

    // R4-proven direct epilogue: bias + sigmoid + output + next-step diff
    const int lane = threadIdx.x & 31, wid = threadIdx.x >> 5;
    const int wm = (wid & 1) * 32, wn = (wid >> 1) * 32;
    const int r = lane >> 2, cp = (lane & 3) * 2;
    const bool hasnext = (t + 1 < T_);

#pragma unroll
    for (int mf = 0; mf < 2; ++mf)
#pragma unroll
        for (int nf = 0; nf < 4; ++nf) {
            const int n = n0 + wn + nf * 8 + cp;
            const float bo0 = b_out[n], bo1 = b_out[n + 1];
#pragma unroll
            for (int hm = 0; hm < 2; ++hm) {
                const int m = m0 + wm + mf * 16 + r + hm * 8;
                float v0 = acc[mf][nf][hm * 2 + 0] + bo0;
                float v1 = acc[mf][nf][hm * 2 + 1] + bo1;
                v0 = 1.f / (1.f + __expf(-v0));
                v1 = 1.f / (1.f + __expf(-v1));
                *(float2*)&out[(size_t)m * (T_ * D_) + (size_t)t * D_ + n] = make_float2(v0, v1);
                if (hasnext) {
                    const float2 xv = *(const float2*)&x[(size_t)m * (T_ * D_) + (size_t)(t + 1) * D_ + n];
                    *(__half2*)&g_diffh[(size_t)m * D_ + n] =
                        __floats2half2_rn(xv.x - v0, xv.y - v1);
                }
            }
        }
}

// ---------------- one-time prep (R2-proven) ----------------
__global__ void convert_k(const float* __restrict__ Z, const float* __restrict__ KF) {
    const int i = blockIdx.x * blockDim.x + threadIdx.x;
    if (i < D_ * H_) {
        g_KFh[i] = __float2half(KF[i]);
        g_Zh[i]  = __float2half(Z[i]);
    }
}

// Step-0 diff: nb0 = b_out broadcast (no sigmoid on step 0, per reference)
__global__ void init_k(const float* __restrict__ x, const float* __restrict__ bo) {
    const int i = blockIdx.x * blockDim.x + threadIdx.x;  // over B_*D_
    const int b = i >> 12;
    const int k = i & (D_ - 1);
    g_diffh[i] = __float2half(x[(size_t)b * (T_ * D_) + k] - bo[k]);
}

extern "C" void kernel_launch(void* const* d_in, const int* in_sizes, int n_in,
                              void* d_out, int out_size) {
    const float* x  = (const float*)d_in[0];   // [B,T,D]
    const float* Z  = (const float*)d_in[1];   // [H,D]
    const float* bo = (const float*)d_in[2];   // [D]
    const float* KF = (const float*)d_in[3];   // [D,H]
    const float* bh = (const float*)d_in[4];   // [H]
    float* out = (float*)d_out;                // [B,T,D]

    convert_k<<<(D_ * H_ + 255) / 256, 256>>>(Z, KF);
    init_k<<<(B_ * D_ + 255) / 256, 256>>>(x, bo);

    dim3 g1(H_ / BN, B_ / BM, SPLIT1);  // (16, 4, 4) = 256 CTAs
    dim3 g2(D_ / BN, B_ / BM);          // (64, 4)    = 256 CTAs
    for (int t = 0; t < T_; ++t) {
        gemm1_k<<<g1, NTH>>>(bh);
        gemm2_k<<<g2, NTH>>>(x, bo, out, t);
    }
}